// round 16
// baseline (speedup 1.0000x reference)
#include <cuda_runtime.h>
#include <math.h>

// Fixed problem shapes
#define NN     20000
#define EE     320000
#define INC    128
#define L1C    256   // HEADS*HID (layer-1 width)
#define L2C    64    // layer-2 width
#define MAXDEG 128   // padded CSR bucket size (P(deg>128) ~ 0 for Poisson(16))

#define LOG2E 1.4426950408889634f

typedef unsigned long long u64;

// ---------------- static device scratch (16B aligned for vector access) ------
__device__ __align__(16) float g_xl1[NN * L1C];
__device__ __align__(16) float g_xr1[NN * L1C];
__device__ __align__(16) float g_h  [NN * L1C];
__device__ __align__(16) float g_xl2[NN * L2C];
__device__ __align__(16) float g_xr2[NN * L2C];
__device__ int   g_cursor[NN];
__device__ __align__(16) int2 g_csr[NN * MAXDEG];   // (src, eid) per dst bucket

// ---------------- f32x2 helpers ----------------
__device__ __forceinline__ u64 pk2(float lo, float hi) {
    u64 r; asm("mov.b64 %0, {%1,%2};" : "=l"(r) : "f"(lo), "f"(hi)); return r;
}
__device__ __forceinline__ u64 dup2(float v) { return pk2(v, v); }
__device__ __forceinline__ void upk2(float& lo, float& hi, u64 v) {
    asm("mov.b64 {%0,%1}, %2;" : "=f"(lo), "=f"(hi) : "l"(v));
}
__device__ __forceinline__ u64 fma2(u64 a, u64 b, u64 c) {
    u64 d; asm("fma.rn.f32x2 %0, %1, %2, %3;" : "=l"(d) : "l"(a), "l"(b), "l"(c)); return d;
}
__device__ __forceinline__ u64 add2(u64 a, u64 b) {
    u64 d; asm("add.rn.f32x2 %0, %1, %2;" : "=l"(d) : "l"(a), "l"(b)); return d;
}
__device__ __forceinline__ u64 mul2(u64 a, u64 b) {
    u64 d; asm("mul.rn.f32x2 %0, %1, %2;" : "=l"(d) : "l"(a), "l"(b)); return d;
}

// ---------------- padded-bucket CSR scatter (cursor pre-zeroed by memset) ----
__global__ void k_scatter(const int* __restrict__ src, const int* __restrict__ dst) {
    int e = blockIdx.x * blockDim.x + threadIdx.x;
    if (e < EE) {
        int d = dst[e];
        int slot = atomicAdd(&g_cursor[d], 1);
        if (slot < MAXDEG) g_csr[d * MAXDEG + slot] = make_int2(src[e], e);
    }
}

// ---------------- dual-output SGEMM body (single-buffer, conflict-free) ------
__device__ __forceinline__
void gemm_dual_body(const float* __restrict__ A, int M, int K,
                    const float* __restrict__ B0, const float* __restrict__ B1,
                    int ncols, int split,
                    float* __restrict__ out0, float* __restrict__ out1)
{
    __shared__ float As[16][132];
    __shared__ float Bs[16][128];
    const int tid = threadIdx.x;
    const int tx = tid & 15, ty = tid >> 4;
    const int row0 = blockIdx.y * 128;
    const int n0 = blockIdx.x * 128;
    const int w0 = split, w1 = ncols - split;

    u64 acc[8][4];
#pragma unroll
    for (int i = 0; i < 8; i++)
#pragma unroll
        for (int j = 0; j < 4; j++) acc[i][j] = 0ull;

    const int ar = tid >> 2;        // 0..63
    const int ac = (tid & 3) * 4;   // 0,4,8,12
    const int bk = tid >> 5;        // 0..7
    const int bc = (tid & 31) * 4;  // 0..124

    for (int k0 = 0; k0 < K; k0 += 16) {
#pragma unroll
        for (int p = 0; p < 2; p++) {
            int r = ar + p * 64;
            int gr = row0 + r;
            float4 v = make_float4(0.f, 0.f, 0.f, 0.f);
            if (gr < M) v = *(const float4*)(A + (size_t)gr * K + k0 + ac);
            As[ac + 0][r] = v.x; As[ac + 1][r] = v.y;
            As[ac + 2][r] = v.z; As[ac + 3][r] = v.w;
        }
#pragma unroll
        for (int p = 0; p < 2; p++) {
            int kk = bk + p * 8;
            int gc = n0 + bc;
            const float* srcp = (gc < w0)
                ? (B0 + (size_t)(k0 + kk) * w0 + gc)
                : (B1 + (size_t)(k0 + kk) * w1 + (gc - w0));
            *(float4*)&Bs[kk][bc] = *(const float4*)srcp;
        }
        __syncthreads();
#pragma unroll
        for (int k = 0; k < 16; k++) {
            float4 a0 = *(float4*)&As[k][ty * 4];
            float4 a1 = *(float4*)&As[k][64 + ty * 4];
            float4 bv0 = *(float4*)&Bs[k][tx * 4];
            float4 bv1 = *(float4*)&Bs[k][64 + tx * 4];
            u64 bp[4] = { pk2(bv0.x, bv0.y), pk2(bv0.z, bv0.w),
                          pk2(bv1.x, bv1.y), pk2(bv1.z, bv1.w) };
            float av[8] = { a0.x, a0.y, a0.z, a0.w, a1.x, a1.y, a1.z, a1.w };
#pragma unroll
            for (int i = 0; i < 8; i++) {
                u64 ap = dup2(av[i]);
#pragma unroll
                for (int j = 0; j < 4; j++) acc[i][j] = fma2(ap, bp[j], acc[i][j]);
            }
        }
        __syncthreads();
    }
#pragma unroll
    for (int i = 0; i < 8; i++) {
        int gr = row0 + ((i < 4) ? (ty * 4 + i) : (64 + ty * 4 + (i - 4)));
        if (gr >= M) continue;
#pragma unroll
        for (int j = 0; j < 4; j++) {
            int gc = n0 + ((j < 2) ? (tx * 4 + 2 * j) : (64 + tx * 4 + 2 * (j - 2)));
            float lo, hi; upk2(lo, hi, acc[i][j]);
            float2 v = make_float2(lo, hi);
            if (gc < w0) *(float2*)(out0 + (size_t)gr * w0 + gc) = v;
            else         *(float2*)(out1 + (size_t)gr * w1 + (gc - w0)) = v;
        }
    }
}

__global__ __launch_bounds__(256, 2)
void k_gemm_xl1(const float* __restrict__ x, const float* __restrict__ Wl1) {
    gemm_dual_body(x, NN, INC, Wl1, Wl1, L1C, L1C, g_xl1, g_xl1);
}
__global__ __launch_bounds__(256, 2)
void k_gemm_xr1(const float* __restrict__ x, const float* __restrict__ Wr1) {
    gemm_dual_body(x, NN, INC, Wr1, Wr1, L1C, L1C, g_xr1, g_xr1);
}
__global__ __launch_bounds__(256, 2)
void k_gemm_l2(const float* __restrict__ Wl2, const float* __restrict__ Wr2) {
    gemm_dual_body(g_h, NN, L1C, Wl2, Wr2, 2 * L2C, L2C, g_xl2, g_xr2);
}

// ---------------- Layer-1 edge pass: 2 warps/node, 4 ch/lane, f32x2 ----------
// Warp part p covers heads 2p, 2p+1. Lane half (lane>>4) selects head;
// (lane&15)*4 its 4 contiguous channels. ev broadcast once per warp; 4-shfl
// butterfly reduces both heads at once. Occupancy pinned at 3 blocks/SM;
// fma chain split into two independent 8-deep halves.
__global__ __launch_bounds__(256, 3)
void k_edge1(const float* __restrict__ eattr,   // [E,16]
             const float* __restrict__ Wep,     // [16,256]
             const float* __restrict__ attp,    // [4,64]
             const float* __restrict__ biasp)   // [256]
{
    const int w    = (blockIdx.x * blockDim.x + threadIdx.x) >> 5;
    const int lane = threadIdx.x & 31;
    const int node = w >> 1;
    const int p    = w & 1;
    if (node >= NN) return;
    const int head = p * 2 + (lane >> 4);
    const int co   = head * 64 + (lane & 15) * 4;   // 4 contiguous channels

    u64 we[16][2];
#pragma unroll
    for (int k = 0; k < 16; k++) {
        ulonglong2 t = *(const ulonglong2*)(Wep + k * 256 + co);
        we[k][0] = t.x; we[k][1] = t.y;
    }
    float4 attv = *(const float4*)(attp + co);
    attv.x *= LOG2E; attv.y *= LOG2E; attv.z *= LOG2E; attv.w *= LOG2E;
    ulonglong2 xrt = *(const ulonglong2*)(g_xr1 + (size_t)node * 256 + co);
    u64 xr0 = xrt.x, xr1v = xrt.y;

    u64 acc0 = 0ull, acc1 = 0ull;
    float m = -1e30f, s = 0.f;

    const int beg = node * MAXDEG;
    const int end = beg + g_cursor[node];

    for (int i = beg; i < end; i++) {
        const int2 se = g_csr[i];
        float ev = (lane < 16) ? eattr[(size_t)se.y * 16 + lane] : 0.f;
        ulonglong2 xlt = *(const ulonglong2*)(g_xl1 + (size_t)se.x * 256 + co);
        u64 xl0 = xlt.x, xl1v = xlt.y;

        // two independent 8-deep fma chains per u (halved serial latency)
        u64 u0a = add2(xl0, xr0),  u0b = 0ull;
        u64 u1a = add2(xl1v, xr1v), u1b = 0ull;
#pragma unroll
        for (int k = 0; k < 8; k++) {
            u64 ekpA = dup2(__shfl_sync(0xffffffffu, ev, k));
            u64 ekpB = dup2(__shfl_sync(0xffffffffu, ev, k + 8));
            u0a = fma2(ekpA, we[k][0], u0a);
            u1a = fma2(ekpA, we[k][1], u1a);
            u0b = fma2(ekpB, we[k + 8][0], u0b);
            u1b = fma2(ekpB, we[k + 8][1], u1b);
        }
        u64 u0 = add2(u0a, u0b);
        u64 u1 = add2(u1a, u1b);

        float f0, f1, f2, f3;
        upk2(f0, f1, u0); upk2(f2, f3, u1);
        f0 = (f0 > 0.f) ? f0 : 0.2f * f0;
        f1 = (f1 > 0.f) ? f1 : 0.2f * f1;
        f2 = (f2 > 0.f) ? f2 : 0.2f * f2;
        f3 = (f3 > 0.f) ? f3 : 0.2f * f3;
        float lg = f0 * attv.x + f1 * attv.y + f2 * attv.z + f3 * attv.w;
#pragma unroll
        for (int off = 8; off > 0; off >>= 1)
            lg += __shfl_xor_sync(0xffffffffu, lg, off);

        float nm = fmaxf(m, lg);
        float sc = exp2f(m - nm);
        float pr = exp2f(lg - nm);
        s = s * sc + pr;
        m = nm;
        u64 prp = dup2(pr), scp = dup2(sc);
        acc0 = fma2(prp, xl0, mul2(acc0, scp));
        acc1 = fma2(prp, xl1v, mul2(acc1, scp));
    }

    // normalize + bias + ELU (one STG.128)
    float a0, a1, a2, a3;
    upk2(a0, a1, acc0); upk2(a2, a3, acc1);
    float inv = (s > 0.f) ? 1.f / s : 0.f;
    float4 bb = *(const float4*)(biasp + co);
    float o0 = a0 * inv + bb.x;
    float o1 = a1 * inv + bb.y;
    float o2 = a2 * inv + bb.z;
    float o3 = a3 * inv + bb.w;
    o0 = (o0 > 0.f) ? o0 : (__expf(o0) - 1.f);
    o1 = (o1 > 0.f) ? o1 : (__expf(o1) - 1.f);
    o2 = (o2 > 0.f) ? o2 : (__expf(o2) - 1.f);
    o3 = (o3 > 0.f) ? o3 : (__expf(o3) - 1.f);
    *(float4*)(g_h + (size_t)node * 256 + co) = make_float4(o0, o1, o2, o3);
}

// ---------------- Layer-2 edge pass (R9-verbatim): warp/node, 2-batch --------
__global__ __launch_bounds__(256)
void k_edge2(const float* __restrict__ eattr,   // [E,16]
             const float* __restrict__ Wep,     // [16,64]
             const float* __restrict__ attp,    // [64]
             const float* __restrict__ biasp,   // [64]
             float* __restrict__ outp)          // [N,64]
{
    const int node = (blockIdx.x * blockDim.x + threadIdx.x) >> 5;
    const int lane = threadIdx.x & 31;
    if (node >= NN) return;
    const int co = 2 * lane;

    float2 we[16];
#pragma unroll
    for (int k = 0; k < 16; k++) we[k] = *(const float2*)(Wep + k * 64 + co);
    float2 attv = *(const float2*)(attp + co);
    attv.x *= LOG2E; attv.y *= LOG2E;
    float2 xrv = *(const float2*)(g_xr2 + (size_t)node * 64 + co);

    float2 accA = make_float2(0.f, 0.f), accB = make_float2(0.f, 0.f);
    float mA = -1e30f, sA = 0.f, mB = -1e30f, sB = 0.f;

    const int beg = node * MAXDEG;
    const int end = beg + g_cursor[node];

    int i = beg;
    for (; i + 1 < end; i += 2) {
        const int2 seA = g_csr[i];
        const int2 seB = g_csr[i + 1];
        float evA = (lane < 16) ? eattr[(size_t)seA.y * 16 + lane] : 0.f;
        float evB = (lane < 16) ? eattr[(size_t)seB.y * 16 + lane] : 0.f;
        float2 xlA = *(const float2*)(g_xl2 + (size_t)seA.x * 64 + co);
        float2 xlB = *(const float2*)(g_xl2 + (size_t)seB.x * 64 + co);

        float uxA = xlA.x + xrv.x, uyA = xlA.y + xrv.y;
        float uxB = xlB.x + xrv.x, uyB = xlB.y + xrv.y;
#pragma unroll
        for (int k = 0; k < 16; k++) {
            float ekA = __shfl_sync(0xffffffffu, evA, k);
            float ekB = __shfl_sync(0xffffffffu, evB, k);
            uxA = fmaf(ekA, we[k].x, uxA);
            uyA = fmaf(ekA, we[k].y, uyA);
            uxB = fmaf(ekB, we[k].x, uxB);
            uyB = fmaf(ekB, we[k].y, uyB);
        }
        uxA = (uxA > 0.f) ? uxA : 0.2f * uxA;  uyA = (uyA > 0.f) ? uyA : 0.2f * uyA;
        uxB = (uxB > 0.f) ? uxB : 0.2f * uxB;  uyB = (uyB > 0.f) ? uyB : 0.2f * uyB;
        float lgA = uxA * attv.x + uyA * attv.y;
        float lgB = uxB * attv.x + uyB * attv.y;
#pragma unroll
        for (int off = 16; off > 0; off >>= 1) {
            lgA += __shfl_xor_sync(0xffffffffu, lgA, off);
            lgB += __shfl_xor_sync(0xffffffffu, lgB, off);
        }
        {
            float nm = fmaxf(mA, lgA);
            float sc = exp2f(mA - nm);
            float p  = exp2f(lgA - nm);
            sA = sA * sc + p;
            mA = nm;
            accA.x = fmaf(p, xlA.x, accA.x * sc);
            accA.y = fmaf(p, xlA.y, accA.y * sc);
        }
        {
            float nm = fmaxf(mB, lgB);
            float sc = exp2f(mB - nm);
            float p  = exp2f(lgB - nm);
            sB = sB * sc + p;
            mB = nm;
            accB.x = fmaf(p, xlB.x, accB.x * sc);
            accB.y = fmaf(p, xlB.y, accB.y * sc);
        }
    }
    if (i < end) {
        const int2 se = g_csr[i];
        float ev = (lane < 16) ? eattr[(size_t)se.y * 16 + lane] : 0.f;
        float2 xlv = *(const float2*)(g_xl2 + (size_t)se.x * 64 + co);
        float ux = xlv.x + xrv.x, uy = xlv.y + xrv.y;
#pragma unroll
        for (int k = 0; k < 16; k++) {
            float ek = __shfl_sync(0xffffffffu, ev, k);
            ux = fmaf(ek, we[k].x, ux);
            uy = fmaf(ek, we[k].y, uy);
        }
        ux = (ux > 0.f) ? ux : 0.2f * ux;
        uy = (uy > 0.f) ? uy : 0.2f * uy;
        float lg = ux * attv.x + uy * attv.y;
#pragma unroll
        for (int off = 16; off > 0; off >>= 1)
            lg += __shfl_xor_sync(0xffffffffu, lg, off);
        float nm = fmaxf(mA, lg);
        float sc = exp2f(mA - nm);
        float p  = exp2f(lg - nm);
        sA = sA * sc + p;
        mA = nm;
        accA.x = fmaf(p, xlv.x, accA.x * sc);
        accA.y = fmaf(p, xlv.y, accA.y * sc);
    }
    {
        float nm = fmaxf(mA, mB);
        float scA = exp2f(mA - nm);
        float scB = exp2f(mB - nm);
        sA = sA * scA + sB * scB;
        accA.x = accA.x * scA + accB.x * scB;
        accA.y = accA.y * scA + accB.y * scB;
    }

    float inv = (sA > 0.f) ? 1.f / sA : 0.f;
    float2 bb = *(const float2*)(biasp + co);
    *(float2*)(outp + (size_t)node * 64 + co) =
        make_float2(accA.x * inv + bb.x, accA.y * inv + bb.y);
}

// ---------------- launch ----------------
extern "C" void kernel_launch(void* const* d_in, const int* in_sizes, int n_in,
                              void* d_out, int out_size) {
    const float* x     = (const float*)d_in[0];
    const int*   ei    = (const int*)d_in[1];
    const float* eattr = (const float*)d_in[2];
    const float* Wl1   = (const float*)d_in[3];
    const float* Wr1   = (const float*)d_in[4];
    const float* We1   = (const float*)d_in[5];
    const float* att1  = (const float*)d_in[6];
    const float* b1    = (const float*)d_in[7];
    const float* Wl2   = (const float*)d_in[8];
    const float* Wr2   = (const float*)d_in[9];
    const float* We2   = (const float*)d_in[10];
    const float* att2  = (const float*)d_in[11];
    const float* b2    = (const float*)d_in[12];
    float* out = (float*)d_out;

    const int* src = ei;
    const int* dst = ei + EE;

    // Zero the per-dst cursors (memset node, not a kernel launch).
    void* cursor_addr = nullptr;
    cudaGetSymbolAddress(&cursor_addr, g_cursor);
    cudaMemsetAsync(cursor_addr, 0, NN * sizeof(int));

    // Launch #0: padded-bucket CSR scatter
    k_scatter<<<(EE + 255) / 256, 256>>>(src, dst);

    // Launches #1,#2: layer-1 projections (edge1 stays at capture index 3)
    {
        dim3 grid(2, (NN + 127) / 128);
        k_gemm_xl1<<<grid, 256>>>(x, Wl1);
        k_gemm_xr1<<<grid, 256>>>(x, Wr1);
    }

    // Launch #3: layer-1 edge pass (2 warps/node, occ-pinned) — capture target
    k_edge1<<<(NN * 2 * 32 + 255) / 256, 256>>>(eattr, We1, att1, b1);

    // Launch #4: layer-2 fused projections
    {
        dim3 grid(1, (NN + 127) / 128);
        k_gemm_l2<<<grid, 256>>>(Wl2, Wr2);
    }

    // Launch #5: layer-2 edge pass -> output
    k_edge2<<<(NN * 32 + 255) / 256, 256>>>(eattr, We2, att2, b2, out);
}

// round 17
// speedup vs baseline: 1.2331x; 1.2331x over previous
#include <cuda_runtime.h>
#include <math.h>

// Fixed problem shapes
#define NN     20000
#define EE     320000
#define INC    128
#define L1C    256   // HEADS*HID (layer-1 width)
#define L2C    64    // layer-2 width
#define MAXDEG 128   // padded CSR bucket size (P(deg>128) ~ 0 for Poisson(16))

#define LOG2E 1.4426950408889634f

typedef unsigned long long u64;

// ---------------- static device scratch (16B aligned for vector access) ------
__device__ __align__(16) float g_xl1[NN * L1C];
__device__ __align__(16) float g_xr1[NN * L1C];
__device__ __align__(16) float g_h  [NN * L1C];
__device__ __align__(16) float g_xl2[NN * L2C];
__device__ __align__(16) float g_xr2[NN * L2C];
__device__ int   g_cursor[NN];
__device__ __align__(16) int2 g_csr[NN * MAXDEG];   // (src, eid) per dst bucket

// ---------------- f32x2 helpers ----------------
__device__ __forceinline__ u64 pk2(float lo, float hi) {
    u64 r; asm("mov.b64 %0, {%1,%2};" : "=l"(r) : "f"(lo), "f"(hi)); return r;
}
__device__ __forceinline__ u64 dup2(float v) { return pk2(v, v); }
__device__ __forceinline__ void upk2(float& lo, float& hi, u64 v) {
    asm("mov.b64 {%0,%1}, %2;" : "=f"(lo), "=f"(hi) : "l"(v));
}
__device__ __forceinline__ u64 fma2(u64 a, u64 b, u64 c) {
    u64 d; asm("fma.rn.f32x2 %0, %1, %2, %3;" : "=l"(d) : "l"(a), "l"(b), "l"(c)); return d;
}
__device__ __forceinline__ u64 add2(u64 a, u64 b) {
    u64 d; asm("add.rn.f32x2 %0, %1, %2;" : "=l"(d) : "l"(a), "l"(b)); return d;
}
__device__ __forceinline__ u64 mul2(u64 a, u64 b) {
    u64 d; asm("mul.rn.f32x2 %0, %1, %2;" : "=l"(d) : "l"(a), "l"(b)); return d;
}

// ---------------- padded-bucket CSR scatter (cursor pre-zeroed by memset) ----
__global__ void k_scatter(const int* __restrict__ src, const int* __restrict__ dst) {
    int e = blockIdx.x * blockDim.x + threadIdx.x;
    if (e < EE) {
        int d = dst[e];
        int slot = atomicAdd(&g_cursor[d], 1);
        if (slot < MAXDEG) g_csr[d * MAXDEG + slot] = make_int2(src[e], e);
    }
}

// ---------------- dual-output SGEMM body (single-buffer, conflict-free) ------
__device__ __forceinline__
void gemm_dual_body(const float* __restrict__ A, int M, int K,
                    const float* __restrict__ B0, const float* __restrict__ B1,
                    int ncols, int split,
                    float* __restrict__ out0, float* __restrict__ out1)
{
    __shared__ float As[16][132];
    __shared__ float Bs[16][128];
    const int tid = threadIdx.x;
    const int tx = tid & 15, ty = tid >> 4;
    const int row0 = blockIdx.y * 128;
    const int n0 = blockIdx.x * 128;
    const int w0 = split, w1 = ncols - split;

    u64 acc[8][4];
#pragma unroll
    for (int i = 0; i < 8; i++)
#pragma unroll
        for (int j = 0; j < 4; j++) acc[i][j] = 0ull;

    const int ar = tid >> 2;        // 0..63
    const int ac = (tid & 3) * 4;   // 0,4,8,12
    const int bk = tid >> 5;        // 0..7
    const int bc = (tid & 31) * 4;  // 0..124

    for (int k0 = 0; k0 < K; k0 += 16) {
#pragma unroll
        for (int p = 0; p < 2; p++) {
            int r = ar + p * 64;
            int gr = row0 + r;
            float4 v = make_float4(0.f, 0.f, 0.f, 0.f);
            if (gr < M) v = *(const float4*)(A + (size_t)gr * K + k0 + ac);
            As[ac + 0][r] = v.x; As[ac + 1][r] = v.y;
            As[ac + 2][r] = v.z; As[ac + 3][r] = v.w;
        }
#pragma unroll
        for (int p = 0; p < 2; p++) {
            int kk = bk + p * 8;
            int gc = n0 + bc;
            const float* srcp = (gc < w0)
                ? (B0 + (size_t)(k0 + kk) * w0 + gc)
                : (B1 + (size_t)(k0 + kk) * w1 + (gc - w0));
            *(float4*)&Bs[kk][bc] = *(const float4*)srcp;
        }
        __syncthreads();
#pragma unroll
        for (int k = 0; k < 16; k++) {
            float4 a0 = *(float4*)&As[k][ty * 4];
            float4 a1 = *(float4*)&As[k][64 + ty * 4];
            float4 bv0 = *(float4*)&Bs[k][tx * 4];
            float4 bv1 = *(float4*)&Bs[k][64 + tx * 4];
            u64 bp[4] = { pk2(bv0.x, bv0.y), pk2(bv0.z, bv0.w),
                          pk2(bv1.x, bv1.y), pk2(bv1.z, bv1.w) };
            float av[8] = { a0.x, a0.y, a0.z, a0.w, a1.x, a1.y, a1.z, a1.w };
#pragma unroll
            for (int i = 0; i < 8; i++) {
                u64 ap = dup2(av[i]);
#pragma unroll
                for (int j = 0; j < 4; j++) acc[i][j] = fma2(ap, bp[j], acc[i][j]);
            }
        }
        __syncthreads();
    }
#pragma unroll
    for (int i = 0; i < 8; i++) {
        int gr = row0 + ((i < 4) ? (ty * 4 + i) : (64 + ty * 4 + (i - 4)));
        if (gr >= M) continue;
#pragma unroll
        for (int j = 0; j < 4; j++) {
            int gc = n0 + ((j < 2) ? (tx * 4 + 2 * j) : (64 + tx * 4 + 2 * (j - 2)));
            float lo, hi; upk2(lo, hi, acc[i][j]);
            float2 v = make_float2(lo, hi);
            if (gc < w0) *(float2*)(out0 + (size_t)gr * w0 + gc) = v;
            else         *(float2*)(out1 + (size_t)gr * w1 + (gc - w0)) = v;
        }
    }
}

__global__ __launch_bounds__(256, 2)
void k_gemm_l1(const float* __restrict__ x,
               const float* __restrict__ Wl1, const float* __restrict__ Wr1) {
    gemm_dual_body(x, NN, INC, Wl1, Wr1, 2 * L1C, L1C, g_xl1, g_xr1);
}
__global__ __launch_bounds__(256, 2)
void k_gemm_l2(const float* __restrict__ Wl2, const float* __restrict__ Wr2) {
    gemm_dual_body(g_h, NN, L1C, Wl2, Wr2, 2 * L2C, L2C, g_xl2, g_xr2);
}

// ---------------- Layer-1 edge pass (R15-exact + ldcg): 2 warps/node ---------
// Warp part p covers heads 2p, 2p+1. Lane half (lane>>4) selects head;
// (lane&15)*4 its 4 contiguous channels. ev broadcast once per warp; 4-shfl
// butterfly reduces both heads at once.
__global__ __launch_bounds__(256)
void k_edge1(const float* __restrict__ eattr,   // [E,16]
             const float* __restrict__ Wep,     // [16,256]
             const float* __restrict__ attp,    // [4,64]
             const float* __restrict__ biasp)   // [256]
{
    const int w    = (blockIdx.x * blockDim.x + threadIdx.x) >> 5;
    const int lane = threadIdx.x & 31;
    const int node = w >> 1;
    const int p    = w & 1;
    if (node >= NN) return;
    const int head = p * 2 + (lane >> 4);
    const int co   = head * 64 + (lane & 15) * 4;   // 4 contiguous channels

    u64 we[16][2];
#pragma unroll
    for (int k = 0; k < 16; k++) {
        ulonglong2 t = *(const ulonglong2*)(Wep + k * 256 + co);
        we[k][0] = t.x; we[k][1] = t.y;
    }
    float4 attv = *(const float4*)(attp + co);
    attv.x *= LOG2E; attv.y *= LOG2E; attv.z *= LOG2E; attv.w *= LOG2E;
    ulonglong2 xrt = *(const ulonglong2*)(g_xr1 + (size_t)node * 256 + co);
    u64 xr0 = xrt.x, xr1v = xrt.y;

    u64 acc0 = 0ull, acc1 = 0ull;
    float m = -1e30f, s = 0.f;

    const int beg = node * MAXDEG;
    const int end = beg + g_cursor[node];

    for (int i = beg; i < end; i++) {
        const int2 se = g_csr[i];
        float ev = (lane < 16) ? eattr[(size_t)se.y * 16 + lane] : 0.f;
        // scattered gather: L2-only (no L1 reuse; keep L1 for eattr/csr)
        ulonglong2 xlt = __ldcg((const ulonglong2*)(g_xl1 + (size_t)se.x * 256 + co));
        u64 xl0 = xlt.x, xl1v = xlt.y;

        u64 u0 = add2(xl0, xr0);
        u64 u1 = add2(xl1v, xr1v);
#pragma unroll
        for (int k = 0; k < 16; k++) {
            u64 ekp = dup2(__shfl_sync(0xffffffffu, ev, k));
            u0 = fma2(ekp, we[k][0], u0);
            u1 = fma2(ekp, we[k][1], u1);
        }
        float f0, f1, f2, f3;
        upk2(f0, f1, u0); upk2(f2, f3, u1);
        f0 = (f0 > 0.f) ? f0 : 0.2f * f0;
        f1 = (f1 > 0.f) ? f1 : 0.2f * f1;
        f2 = (f2 > 0.f) ? f2 : 0.2f * f2;
        f3 = (f3 > 0.f) ? f3 : 0.2f * f3;
        float lg = f0 * attv.x + f1 * attv.y + f2 * attv.z + f3 * attv.w;
#pragma unroll
        for (int off = 8; off > 0; off >>= 1)
            lg += __shfl_xor_sync(0xffffffffu, lg, off);

        float nm = fmaxf(m, lg);
        float sc = exp2f(m - nm);
        float pr = exp2f(lg - nm);
        s = s * sc + pr;
        m = nm;
        u64 prp = dup2(pr), scp = dup2(sc);
        acc0 = fma2(prp, xl0, mul2(acc0, scp));
        acc1 = fma2(prp, xl1v, mul2(acc1, scp));
    }

    // normalize + bias + ELU (one STG.128)
    float a0, a1, a2, a3;
    upk2(a0, a1, acc0); upk2(a2, a3, acc1);
    float inv = (s > 0.f) ? 1.f / s : 0.f;
    float4 bb = *(const float4*)(biasp + co);
    float o0 = a0 * inv + bb.x;
    float o1 = a1 * inv + bb.y;
    float o2 = a2 * inv + bb.z;
    float o3 = a3 * inv + bb.w;
    o0 = (o0 > 0.f) ? o0 : (__expf(o0) - 1.f);
    o1 = (o1 > 0.f) ? o1 : (__expf(o1) - 1.f);
    o2 = (o2 > 0.f) ? o2 : (__expf(o2) - 1.f);
    o3 = (o3 > 0.f) ? o3 : (__expf(o3) - 1.f);
    *(float4*)(g_h + (size_t)node * 256 + co) = make_float4(o0, o1, o2, o3);
}

// ---------------- Layer-2 edge pass (R9 + ldcg): warp/node, 2-batch ----------
__global__ __launch_bounds__(256)
void k_edge2(const float* __restrict__ eattr,   // [E,16]
             const float* __restrict__ Wep,     // [16,64]
             const float* __restrict__ attp,    // [64]
             const float* __restrict__ biasp,   // [64]
             float* __restrict__ outp)          // [N,64]
{
    const int node = (blockIdx.x * blockDim.x + threadIdx.x) >> 5;
    const int lane = threadIdx.x & 31;
    if (node >= NN) return;
    const int co = 2 * lane;

    float2 we[16];
#pragma unroll
    for (int k = 0; k < 16; k++) we[k] = *(const float2*)(Wep + k * 64 + co);
    float2 attv = *(const float2*)(attp + co);
    attv.x *= LOG2E; attv.y *= LOG2E;
    float2 xrv = *(const float2*)(g_xr2 + (size_t)node * 64 + co);

    float2 accA = make_float2(0.f, 0.f), accB = make_float2(0.f, 0.f);
    float mA = -1e30f, sA = 0.f, mB = -1e30f, sB = 0.f;

    const int beg = node * MAXDEG;
    const int end = beg + g_cursor[node];

    int i = beg;
    for (; i + 1 < end; i += 2) {
        const int2 seA = g_csr[i];
        const int2 seB = g_csr[i + 1];
        float evA = (lane < 16) ? eattr[(size_t)seA.y * 16 + lane] : 0.f;
        float evB = (lane < 16) ? eattr[(size_t)seB.y * 16 + lane] : 0.f;
        float2 xlA = __ldcg((const float2*)(g_xl2 + (size_t)seA.x * 64 + co));
        float2 xlB = __ldcg((const float2*)(g_xl2 + (size_t)seB.x * 64 + co));

        float uxA = xlA.x + xrv.x, uyA = xlA.y + xrv.y;
        float uxB = xlB.x + xrv.x, uyB = xlB.y + xrv.y;
#pragma unroll
        for (int k = 0; k < 16; k++) {
            float ekA = __shfl_sync(0xffffffffu, evA, k);
            float ekB = __shfl_sync(0xffffffffu, evB, k);
            uxA = fmaf(ekA, we[k].x, uxA);
            uyA = fmaf(ekA, we[k].y, uyA);
            uxB = fmaf(ekB, we[k].x, uxB);
            uyB = fmaf(ekB, we[k].y, uyB);
        }
        uxA = (uxA > 0.f) ? uxA : 0.2f * uxA;  uyA = (uyA > 0.f) ? uyA : 0.2f * uyA;
        uxB = (uxB > 0.f) ? uxB : 0.2f * uxB;  uyB = (uyB > 0.f) ? uyB : 0.2f * uyB;
        float lgA = uxA * attv.x + uyA * attv.y;
        float lgB = uxB * attv.x + uyB * attv.y;
#pragma unroll
        for (int off = 16; off > 0; off >>= 1) {
            lgA += __shfl_xor_sync(0xffffffffu, lgA, off);
            lgB += __shfl_xor_sync(0xffffffffu, lgB, off);
        }
        {
            float nm = fmaxf(mA, lgA);
            float sc = exp2f(mA - nm);
            float p  = exp2f(lgA - nm);
            sA = sA * sc + p;
            mA = nm;
            accA.x = fmaf(p, xlA.x, accA.x * sc);
            accA.y = fmaf(p, xlA.y, accA.y * sc);
        }
        {
            float nm = fmaxf(mB, lgB);
            float sc = exp2f(mB - nm);
            float p  = exp2f(lgB - nm);
            sB = sB * sc + p;
            mB = nm;
            accB.x = fmaf(p, xlB.x, accB.x * sc);
            accB.y = fmaf(p, xlB.y, accB.y * sc);
        }
    }
    if (i < end) {
        const int2 se = g_csr[i];
        float ev = (lane < 16) ? eattr[(size_t)se.y * 16 + lane] : 0.f;
        float2 xlv = __ldcg((const float2*)(g_xl2 + (size_t)se.x * 64 + co));
        float ux = xlv.x + xrv.x, uy = xlv.y + xrv.y;
#pragma unroll
        for (int k = 0; k < 16; k++) {
            float ek = __shfl_sync(0xffffffffu, ev, k);
            ux = fmaf(ek, we[k].x, ux);
            uy = fmaf(ek, we[k].y, uy);
        }
        ux = (ux > 0.f) ? ux : 0.2f * ux;
        uy = (uy > 0.f) ? uy : 0.2f * uy;
        float lg = ux * attv.x + uy * attv.y;
#pragma unroll
        for (int off = 16; off > 0; off >>= 1)
            lg += __shfl_xor_sync(0xffffffffu, lg, off);
        float nm = fmaxf(mA, lg);
        float sc = exp2f(mA - nm);
        float p  = exp2f(lg - nm);
        sA = sA * sc + p;
        mA = nm;
        accA.x = fmaf(p, xlv.x, accA.x * sc);
        accA.y = fmaf(p, xlv.y, accA.y * sc);
    }
    {
        float nm = fmaxf(mA, mB);
        float scA = exp2f(mA - nm);
        float scB = exp2f(mB - nm);
        sA = sA * scA + sB * scB;
        accA.x = accA.x * scA + accB.x * scB;
        accA.y = accA.y * scA + accB.y * scB;
    }

    float inv = (sA > 0.f) ? 1.f / sA : 0.f;
    float2 bb = *(const float2*)(biasp + co);
    *(float2*)(outp + (size_t)node * 64 + co) =
        make_float2(accA.x * inv + bb.x, accA.y * inv + bb.y);
}

// ---------------- launch ----------------
extern "C" void kernel_launch(void* const* d_in, const int* in_sizes, int n_in,
                              void* d_out, int out_size) {
    const float* x     = (const float*)d_in[0];
    const int*   ei    = (const int*)d_in[1];
    const float* eattr = (const float*)d_in[2];
    const float* Wl1   = (const float*)d_in[3];
    const float* Wr1   = (const float*)d_in[4];
    const float* We1   = (const float*)d_in[5];
    const float* att1  = (const float*)d_in[6];
    const float* b1    = (const float*)d_in[7];
    const float* Wl2   = (const float*)d_in[8];
    const float* Wr2   = (const float*)d_in[9];
    const float* We2   = (const float*)d_in[10];
    const float* att2  = (const float*)d_in[11];
    const float* b2    = (const float*)d_in[12];
    float* out = (float*)d_out;

    const int* src = ei;
    const int* dst = ei + EE;

    // Zero the per-dst cursors (memset node, not a kernel launch).
    void* cursor_addr = nullptr;
    cudaGetSymbolAddress(&cursor_addr, g_cursor);
    cudaMemsetAsync(cursor_addr, 0, NN * sizeof(int));

    // Launch #0: padded-bucket CSR scatter
    k_scatter<<<(EE + 255) / 256, 256>>>(src, dst);

    // Launch #1: layer-1 fused projections: [20000,128] @ [128, 256|256]
    {
        dim3 grid(4, (NN + 127) / 128);
        k_gemm_l1<<<grid, 256>>>(x, Wl1, Wr1);
    }

    // Launch #2: layer-1 edge pass (2 warps/node, R15-exact + ldcg)
    k_edge1<<<(NN * 2 * 32 + 255) / 256, 256>>>(eattr, We1, att1, b1);

    // Launch #3: layer-2 fused projections — ncu capture target this round
    {
        dim3 grid(1, (NN + 127) / 128);
        k_gemm_l2<<<grid, 256>>>(Wl2, Wr2);
    }

    // Launch #4: layer-2 edge pass -> output
    k_edge2<<<(NN * 32 + 255) / 256, 256>>>(eattr, We2, att2, b2, out);
}